// round 8
// baseline (speedup 1.0000x reference)
#include <cuda_runtime.h>

// ---------------- problem constants ----------------
#define HW      4096
#define NPIX    (HW*HW)
#define NPATCH  64
#define K1      31458u   // loop1 continues iff count(v>th) <= 31457  <=>  v_(31458) <= th
#define K2      20972u   // loop2 continues iff count(v>th) >= 20972  <=>  v_(20972) >  th

// value window (verified per-patch; exact fallback if violated)
#define WLO     0x3F0E0000u   // ~0.5547
#define WHI     0x3F1A0000u   // ~0.6016
#define NW1     768           // level-1 bins of 1024 keys each
#define W1SHIFT 10

#define RPB     32            // rows per blur block
#define NBLK    1024          // blur blocks (8 x 128)
#define CAP     4096          // list capacity per blur block

// ---------------- device scratch ----------------
__device__ float        g_blur[NPIX];
__device__ unsigned int g_listblk[NBLK * CAP];   // 16 MB: per-block in-window keys
__device__ unsigned int g_listcnt[NBLK];
__device__ unsigned int g_whist[NPATCH][NW1];
__device__ unsigned int g_above[NPATCH];         // count(key >= WHI)
__device__ int          g_need [NPATCH];         // exact-fallback flag
__device__ unsigned int g_sub  [NPATCH][2][1024];
__device__ unsigned int g_sel  [NPATCH][4];      // bin1, above1, bin2, above2
__device__ unsigned int g_key  [NPATCH][2];
__device__ float        g_th   [NPATCH];

// ---------------- K0: zero scratch ----------------
__global__ void zero_k() {
    int i = blockIdx.x * 256 + threadIdx.x;
    if (i < NPATCH * 2 * 1024) ((unsigned int*)g_sub)[i] = 0u;
    if (i < NBLK)   g_listcnt[i] = 0u;
    if (i < NPATCH) { g_above[i] = 0u; g_need[i] = 0; }
}

// ---------------- dummy: keeps ncu capture slot on blur_hist ----------------
__global__ void dummy_k() {
    if ((int)threadIdx.x >= 1 << 20) g_need[0] = 0;   // never executes
}

// ---------------- K1: blur (rolling window, 3 LDG.128/row) + list append ----------------
// 128 threads x 4 cols = 512 cols (one patch width), RPB rows per block.
// Per-pixel 25-tap fmaf chain IDENTICAL to the passing version (kw outer, kh inner).
__device__ __forceinline__ void load_row(float* dst, const float* __restrict__ x,
                                         int yy, int c0, bool safe) {
    if (yy < 0 || yy >= HW) {
        #pragma unroll
        for (int j = 0; j < 12; j++) dst[j] = 0.0f;
    } else if (safe) {
        const float4* p = (const float4*)&x[yy * HW + c0 - 4];
        float4 a = __ldg(p), b = __ldg(p + 1), c = __ldg(p + 2);
        dst[0]=a.x; dst[1]=a.y; dst[2]=a.z;  dst[3]=a.w;
        dst[4]=b.x; dst[5]=b.y; dst[6]=b.z;  dst[7]=b.w;
        dst[8]=c.x; dst[9]=c.y; dst[10]=c.z; dst[11]=c.w;
    } else {
        #pragma unroll
        for (int j = 0; j < 12; j++) {
            int cc = c0 - 4 + j;
            dst[j] = (cc >= 0 && cc < HW) ? __ldg(&x[yy * HW + cc]) : 0.0f;
        }
    }
}

__global__ __launch_bounds__(128) void blur_hist(const float* __restrict__ x,
                                                 const float* __restrict__ bk) {
    __shared__ unsigned int scnt;
    __shared__ unsigned int sred[4];
    if (threadIdx.x == 0) scnt = 0u;
    __syncthreads();

    const float w  = bk[0];
    const int   c0 = blockIdx.x * 512 + threadIdx.x * 4;
    const int   y0 = blockIdx.y * RPB;
    const int   patch = ((y0 >> 9) << 3) + (c0 >> 9);
    const int   blk   = blockIdx.y * 8 + blockIdx.x;
    const bool  safe = (c0 >= 4) && (c0 <= HW - 9);
    const int   lane = threadIdx.x & 31;
    unsigned int cntAbove = 0;
    unsigned int* mylist = g_listblk + blk * CAP;

    float f[5][12];
    #pragma unroll
    for (int i = 0; i < 4; i++) load_row(f[i], x, y0 - 2 + i, c0, safe);

    for (int y = y0; y < y0 + RPB; y++) {
        load_row(f[4], x, y + 2, c0, safe);

        float4 o;
        float* op = (float*)&o;
        #pragma unroll
        for (int u = 0; u < 4; u++) {
            float acc = 0.0f;
            #pragma unroll
            for (int j = 0; j < 5; j++)        // kw outer
                #pragma unroll
                for (int i = 0; i < 5; i++)    // kh inner (fastest) — Eigen order
                    acc = fmaf(f[i][u + j + 2], w, acc);
            op[u] = acc;
            unsigned int key = __float_as_uint(acc);
            cntAbove += (key >= WHI) ? 1u : 0u;
            bool inwin = (key >= WLO) && (key < WHI);
            unsigned int m = __ballot_sync(0xffffffffu, inwin);
            if (m) {
                int leader = __ffs(m) - 1;
                unsigned int base = 0;
                if (lane == leader) base = atomicAdd(&scnt, (unsigned)__popc(m));
                base = __shfl_sync(0xffffffffu, base, leader);
                if (inwin) {
                    unsigned int pos = base + __popc(m & ((1u << lane) - 1u));
                    if (pos < CAP) mylist[pos] = key - WLO;
                }
            }
        }
        *(float4*)&g_blur[y * HW + c0] = o;

        #pragma unroll
        for (int i = 0; i < 4; i++)
            #pragma unroll
            for (int j = 0; j < 12; j++)
                f[i][j] = f[i + 1][j];
    }

    #pragma unroll
    for (int off = 16; off; off >>= 1)
        cntAbove += __shfl_down_sync(0xffffffffu, cntAbove, off);
    if (lane == 0) sred[threadIdx.x >> 5] = cntAbove;
    __syncthreads();
    if (threadIdx.x == 0) {
        atomicAdd(&g_above[patch], sred[0] + sred[1] + sred[2] + sred[3]);
        unsigned int n = scnt;
        g_listcnt[blk] = (n <= CAP) ? n : CAP;
        if (n > CAP) g_need[patch] = 1;     // overflow -> exact fallback
    }
}

// ---------------- K1b: level-1 histogram from lists (one block per patch) ----------------
__global__ __launch_bounds__(256) void hist_from_list() {
    __shared__ unsigned int h[NW1];
    const int p = blockIdx.x, t = threadIdx.x;
    for (int i = t; i < NW1; i += 256) h[i] = 0u;
    __syncthreads();
    const int pr = p >> 3, pc = p & 7;
    for (int s = 0; s < 16; s++) {                // 16 blur blocks per patch
        const int blk = (pr * 16 + s) * 8 + pc;
        const unsigned int n = g_listcnt[blk];
        const unsigned int* lst = g_listblk + blk * CAP;
        for (unsigned int i = t; i < n; i += 256)
            atomicAdd(&h[lst[i] >> W1SHIFT], 1u);
    }
    __syncthreads();
    for (int i = t; i < NW1; i += 256) g_whist[p][i] = h[i];
}

// ---------------- K2: locate level-1 bin for each quantile; verify window ----------------
__global__ __launch_bounds__(1024) void coarse_select_win() {
    __shared__ unsigned int ss[1024];
    const int p = blockIdx.x, t = threadIdx.x;
    unsigned int c = (t < NW1) ? g_whist[p][t] : 0u;
    ss[t] = c;
    __syncthreads();
    for (int off = 1; off < 1024; off <<= 1) {   // inclusive suffix scan
        unsigned int v = (t + off < 1024) ? ss[t + off] : 0u;
        __syncthreads();
        ss[t] += v;
        __syncthreads();
    }
    const unsigned int ga = g_above[p];
    const unsigned int total_in = ss[0];
    unsigned int above = ((t < 1023) ? ss[t + 1] : 0u) + ga;

    if (t == 0) {
        if ((ga >= K2) || (ga + total_in < K1)) g_need[p] = 1;  // OR (keep overflow flag)
    }

    if (above < K1 && K1 <= above + c) { g_sel[p][0] = (unsigned)t; g_sel[p][1] = above; }
    if (above < K2 && K2 <= above + c) { g_sel[p][2] = (unsigned)t; g_sel[p][3] = above; }
}

// ---------------- K3a: sub-histogram from lists ----------------
__global__ __launch_bounds__(256) void refine_list() {
    const int blk = blockIdx.x;
    const int p = ((blk >> 3) >> 4) * 8 + (blk & 7);
    const unsigned int bin1 = g_sel[p][0], bin2 = g_sel[p][2];
    const unsigned int n = g_listcnt[blk];
    const unsigned int* lst = g_listblk + blk * CAP;
    for (unsigned int i = threadIdx.x; i < n; i += 256) {
        unsigned int wk = lst[i], bin = wk >> W1SHIFT;
        if (bin == bin1) atomicAdd(&g_sub[p][0][wk & 1023u], 1u);
        if (bin == bin2) atomicAdd(&g_sub[p][1][wk & 1023u], 1u);
    }
}

// ---------------- K3b: exact float-bit key within the level-1 bin ----------------
__global__ __launch_bounds__(1024) void refine_select() {
    __shared__ unsigned int ss[1024];
    const int p = blockIdx.x, t = threadIdx.x;
    if (g_need[p]) return;

    for (int q = 0; q < 2; q++) {
        const unsigned int bin = g_sel[p][q * 2];
        const unsigned int ab  = g_sel[p][q * 2 + 1];
        const unsigned int r   = (q ? K2 : K1) - ab;

        unsigned int c = g_sub[p][q][t];
        ss[t] = c;
        __syncthreads();
        for (int off = 1; off < 1024; off <<= 1) {
            unsigned int v = (t + off < 1024) ? ss[t + off] : 0u;
            __syncthreads();
            ss[t] += v;
            __syncthreads();
        }
        unsigned int above = (t < 1023) ? ss[t + 1] : 0u;
        if (t == 0) g_key[p][q] = WLO + (bin << W1SHIFT);
        __syncthreads();
        if (above < r && r <= above + c)
            g_key[p][q] = WLO + (bin << W1SHIFT) + (unsigned)t;
        __syncthreads();
    }
}

// ---------------- K3c: gated exact fallback (binary search on key) ----------------
__global__ __launch_bounds__(1024) void fb_exact() {
    const int p = blockIdx.x;
    if (!g_need[p]) return;
    __shared__ unsigned int sred[32];
    __shared__ unsigned int scnt2;
    const float* base = g_blur + ((p >> 3) * 512) * HW + (p & 7) * 512;
    const int t = threadIdx.x, lane = t & 31, wid = t >> 5;

    for (int q = 0; q < 2; q++) {
        const unsigned int K = q ? K2 : K1;
        unsigned int lo = 0u, hi = 0x40000000u;
        while (hi - lo > 1u) {
            unsigned int mid = lo + ((hi - lo) >> 1);
            unsigned int cnt = 0;
            for (int i = t; i < 512 * 512; i += 1024) {
                unsigned int key = __float_as_uint(base[(i >> 9) * HW + (i & 511)]);
                cnt += (key >= mid) ? 1u : 0u;
            }
            #pragma unroll
            for (int off = 16; off; off >>= 1)
                cnt += __shfl_down_sync(0xffffffffu, cnt, off);
            if (lane == 0) sred[wid] = cnt;
            __syncthreads();
            if (t == 0) {
                unsigned int s = 0;
                for (int i = 0; i < 32; i++) s += sred[i];
                scnt2 = s;
            }
            __syncthreads();
            if (scnt2 >= K) lo = mid; else hi = mid;
            __syncthreads();
        }
        if (t == 0) g_key[p][q] = lo;
        __syncthreads();
    }
}

// ---------------- K4: sequential threshold walk (bit-faithful, unrolled chain) ----------------
// Same fp operations/comparisons as the reference loops; only control flow is
// restructured (16 dependent steps computed per branch round).
__device__ __forceinline__ float walk_down(float th, float A) {
    for (int g = 0; g < 20000; g++) {
        if (!(A <= th)) return th;
        float t1  = th  - 0.0005f; if (A > t1)  return t1;
        float t2  = t1  - 0.0005f; if (A > t2)  return t2;
        float t3  = t2  - 0.0005f; if (A > t3)  return t3;
        float t4  = t3  - 0.0005f; if (A > t4)  return t4;
        float t5  = t4  - 0.0005f; if (A > t5)  return t5;
        float t6  = t5  - 0.0005f; if (A > t6)  return t6;
        float t7  = t6  - 0.0005f; if (A > t7)  return t7;
        float t8  = t7  - 0.0005f; if (A > t8)  return t8;
        float t9  = t8  - 0.0005f; if (A > t9)  return t9;
        float t10 = t9  - 0.0005f; if (A > t10) return t10;
        float t11 = t10 - 0.0005f; if (A > t11) return t11;
        float t12 = t11 - 0.0005f; if (A > t12) return t12;
        float t13 = t12 - 0.0005f; if (A > t13) return t13;
        float t14 = t13 - 0.0005f; if (A > t14) return t14;
        float t15 = t14 - 0.0005f; if (A > t15) return t15;
        th = t15 - 0.0005f;
    }
    return th;
}
__device__ __forceinline__ float walk_up(float th, float B) {
    for (int g = 0; g < 20000; g++) {
        if (!(B > th)) return th;
        float t1  = th  + 0.0005f; if (B <= t1)  return t1;
        float t2  = t1  + 0.0005f; if (B <= t2)  return t2;
        float t3  = t2  + 0.0005f; if (B <= t3)  return t3;
        float t4  = t3  + 0.0005f; if (B <= t4)  return t4;
        float t5  = t4  + 0.0005f; if (B <= t5)  return t5;
        float t6  = t5  + 0.0005f; if (B <= t6)  return t6;
        float t7  = t6  + 0.0005f; if (B <= t7)  return t7;
        float t8  = t7  + 0.0005f; if (B <= t8)  return t8;
        float t9  = t8  + 0.0005f; if (B <= t9)  return t9;
        float t10 = t9  + 0.0005f; if (B <= t10) return t10;
        float t11 = t10 + 0.0005f; if (B <= t11) return t11;
        float t12 = t11 + 0.0005f; if (B <= t12) return t12;
        float t13 = t12 + 0.0005f; if (B <= t13) return t13;
        float t14 = t13 + 0.0005f; if (B <= t14) return t14;
        float t15 = t14 + 0.0005f; if (B <= t15) return t15;
        th = t15 + 0.0005f;
    }
    return th;
}

__global__ void walk() {
    if (blockIdx.x == 0 && threadIdx.x == 0) {
        float th = 0.5f;
        for (int p = 0; p < NPATCH; p++) {
            float A = __uint_as_float(g_key[p][0]);
            float B = __uint_as_float(g_key[p][1]);
            th = walk_down(th, A);
            th = walk_up(th, B);
            g_th[p] = th;
        }
    }
}

// ---------------- K5: bit-packed binarize + close (dilate5, erode5) ----------------
#define CTW  256
#define CTH  128
#define WPR  10
#define TROWS 136
__global__ __launch_bounds__(256) void close_k(float* __restrict__ out) {
    __shared__ unsigned int A[TROWS][WPR];
    __shared__ unsigned int B[TROWS][WPR];
    __shared__ float sth[NPATCH];
    const int t = threadIdx.x;
    if (t < NPATCH) sth[t] = g_th[t];
    __syncthreads();

    const int gx0 = blockIdx.x * CTW;
    const int gy0 = blockIdx.y * CTH;
    const int lane = t & 31, wid = t >> 5;

    for (int idx = wid; idx < TROWS * WPR; idx += 8) {
        int r = idx / WPR, wc = idx % WPR;
        int gy = gy0 + r - 4;
        int gx = gx0 + (wc - 1) * 32 + lane;
        unsigned int bit = 0;
        if ((unsigned)gy < HW && (unsigned)gx < HW) {
            float bl = g_blur[gy * HW + gx];
            bit = (bl > sth[((gy >> 9) << 3) + (gx >> 9)]) ? 1u : 0u;
        }
        unsigned int word = __ballot_sync(0xffffffffu, bit);
        if (lane == 0) A[r][wc] = word;
    }
    __syncthreads();

    for (int i = t; i < TROWS * WPR; i += 256) {
        int r = i / WPR, wc = i % WPR;
        unsigned int wv = A[r][wc];
        unsigned int lw = wc > 0       ? A[r][wc - 1] : 0u;
        unsigned int rw = wc < WPR - 1 ? A[r][wc + 1] : 0u;
        B[r][wc] = wv | __funnelshift_r(wv, rw, 1) | __funnelshift_r(wv, rw, 2)
                      | __funnelshift_l(lw, wv, 1) | __funnelshift_l(lw, wv, 2);
    }
    __syncthreads();

    for (int i = t; i < TROWS * WPR; i += 256) {
        int r = i / WPR, wc = i % WPR;
        unsigned int d = 0u;
        if (r >= 2 && r < TROWS - 2)
            d = B[r-2][wc] | B[r-1][wc] | B[r][wc] | B[r+1][wc] | B[r+2][wc];
        int gy = gy0 + r - 4;
        bool xout = (wc == 0 && gx0 == 0) || (wc == WPR - 1 && gx0 + CTW == HW);
        if ((unsigned)gy >= HW || xout) d = 0xffffffffu;
        A[r][wc] = d;
    }
    __syncthreads();

    for (int i = t; i < TROWS * WPR; i += 256) {
        int r = i / WPR, wc = i % WPR;
        unsigned int wv = A[r][wc];
        unsigned int lw = wc > 0       ? A[r][wc - 1] : 0xffffffffu;
        unsigned int rw = wc < WPR - 1 ? A[r][wc + 1] : 0xffffffffu;
        B[r][wc] = wv & __funnelshift_r(wv, rw, 1) & __funnelshift_r(wv, rw, 2)
                      & __funnelshift_l(lw, wv, 1) & __funnelshift_l(lw, wv, 2);
    }
    __syncthreads();

    for (int i = t; i < CTH * 8; i += 256) {
        int r = (i >> 3) + 4, wc = (i & 7) + 1;
        unsigned int v = B[r-2][wc] & B[r-1][wc] & B[r][wc] & B[r+1][wc] & B[r+2][wc];
        int gy = gy0 + r - 4;
        int gx = gx0 + (wc - 1) * 32;
        float4* o = (float4*)&out[gy * HW + gx];
        #pragma unroll
        for (int q = 0; q < 8; q++) {
            float4 fv;
            fv.x = (v >> (q * 4 + 0)) & 1u ? 1.0f : 0.0f;
            fv.y = (v >> (q * 4 + 1)) & 1u ? 1.0f : 0.0f;
            fv.z = (v >> (q * 4 + 2)) & 1u ? 1.0f : 0.0f;
            fv.w = (v >> (q * 4 + 3)) & 1u ? 1.0f : 0.0f;
            o[q] = fv;
        }
    }
}

// ---------------- launch ----------------
extern "C" void kernel_launch(void* const* d_in, const int* in_sizes, int n_in,
                              void* d_out, int out_size) {
    const float* x  = (const float*)d_in[0];
    const float* bk = (const float*)d_in[1];
    float* out = (float*)d_out;
    (void)in_sizes; (void)n_in; (void)out_size;

    zero_k<<<(NPATCH * 2 * 1024 + 255) / 256, 256>>>();
    dummy_k<<<1, 32>>>();
    dummy_k<<<1, 32>>>();                       // keeps ncu slot on blur_hist
    blur_hist<<<dim3(HW / 512, HW / RPB), 128>>>(x, bk);
    hist_from_list<<<NPATCH, 256>>>();
    coarse_select_win<<<NPATCH, 1024>>>();
    refine_list<<<NBLK, 256>>>();
    refine_select<<<NPATCH, 1024>>>();
    fb_exact<<<NPATCH, 1024>>>();
    walk<<<1, 32>>>();
    close_k<<<dim3(HW / CTW, HW / CTH), 256>>>(out);
}

// round 9
// speedup vs baseline: 1.0069x; 1.0069x over previous
#include <cuda_runtime.h>

// ---------------- problem constants ----------------
#define HW      4096
#define NPIX    (HW*HW)
#define NPATCH  64
#define K1      31458u   // loop1 continues iff count(v>th) <= 31457  <=>  v_(31458) <= th
#define K2      20972u   // loop2 continues iff count(v>th) >= 20972  <=>  v_(20972) >  th

// value window (verified per-patch; exact fallback if violated)
#define WLO     0x3F0E0000u   // ~0.5547
#define WHI     0x3F1A0000u   // ~0.6016
#define NW1     768           // level-1 bins of 1024 keys each
#define W1SHIFT 10

#define RPB     32            // rows per blur block
#define NBLK    1024          // blur blocks (8 x 128)
#define CAP     4096          // list capacity per blur block

// ---------------- device scratch ----------------
__device__ float        g_blur[NPIX];
__device__ unsigned int g_listblk[NBLK * CAP];   // 16 MB: per-block in-window keys
__device__ unsigned int g_listcnt[NBLK];
__device__ unsigned int g_whist[NPATCH][NW1];
__device__ unsigned int g_above[NPATCH];         // count(key >= WHI)
__device__ int          g_need [NPATCH];         // exact-fallback flag
__device__ unsigned int g_sub  [NPATCH][2][1024];
__device__ unsigned int g_sel  [NPATCH][4];      // bin1, above1, bin2, above2
__device__ unsigned int g_key  [NPATCH][2];
__device__ float        g_th   [NPATCH];

// ---------------- K0: zero scratch ----------------
__global__ void zero_k() {
    int i = blockIdx.x * 256 + threadIdx.x;
    if (i < NPATCH * 2 * 1024) ((unsigned int*)g_sub)[i] = 0u;
    if (i < NBLK)   g_listcnt[i] = 0u;
    if (i < NPATCH) { g_above[i] = 0u; g_need[i] = 0; }
}

// ---------------- dummy: keeps ncu capture slot on blur_hist ----------------
__global__ void dummy_k() {
    if ((int)threadIdx.x >= 1 << 20) g_need[0] = 0;   // never executes
}

// ---------------- K1: blur (rolling window, 3 LDG.128/row) + list append ----------------
// 128 threads x 4 cols = 512 cols (one patch width), RPB rows per block.
// Per-pixel 25-tap fmaf chain IDENTICAL to the passing version (kw outer, kh inner).
__device__ __forceinline__ void load_row(float* dst, const float* __restrict__ x,
                                         int yy, int c0, bool safe) {
    if (yy < 0 || yy >= HW) {
        #pragma unroll
        for (int j = 0; j < 12; j++) dst[j] = 0.0f;
    } else if (safe) {
        const float4* p = (const float4*)&x[yy * HW + c0 - 4];
        float4 a = __ldg(p), b = __ldg(p + 1), c = __ldg(p + 2);
        dst[0]=a.x; dst[1]=a.y; dst[2]=a.z;  dst[3]=a.w;
        dst[4]=b.x; dst[5]=b.y; dst[6]=b.z;  dst[7]=b.w;
        dst[8]=c.x; dst[9]=c.y; dst[10]=c.z; dst[11]=c.w;
    } else {
        #pragma unroll
        for (int j = 0; j < 12; j++) {
            int cc = c0 - 4 + j;
            dst[j] = (cc >= 0 && cc < HW) ? __ldg(&x[yy * HW + cc]) : 0.0f;
        }
    }
}

__global__ __launch_bounds__(128) void blur_hist(const float* __restrict__ x,
                                                 const float* __restrict__ bk) {
    __shared__ unsigned int scnt;
    __shared__ unsigned int sred[4];
    if (threadIdx.x == 0) scnt = 0u;
    __syncthreads();

    const float w  = bk[0];
    const int   c0 = blockIdx.x * 512 + threadIdx.x * 4;
    const int   y0 = blockIdx.y * RPB;
    const int   patch = ((y0 >> 9) << 3) + (c0 >> 9);
    const int   blk   = blockIdx.y * 8 + blockIdx.x;
    const bool  safe = (c0 >= 4) && (c0 <= HW - 9);
    const int   lane = threadIdx.x & 31;
    unsigned int cntAbove = 0;
    unsigned int* mylist = g_listblk + blk * CAP;

    float f[5][12];
    #pragma unroll
    for (int i = 0; i < 4; i++) load_row(f[i], x, y0 - 2 + i, c0, safe);

    for (int y = y0; y < y0 + RPB; y++) {
        load_row(f[4], x, y + 2, c0, safe);

        float4 o;
        float* op = (float*)&o;
        #pragma unroll
        for (int u = 0; u < 4; u++) {
            float acc = 0.0f;
            #pragma unroll
            for (int j = 0; j < 5; j++)        // kw outer
                #pragma unroll
                for (int i = 0; i < 5; i++)    // kh inner (fastest) — Eigen order
                    acc = fmaf(f[i][u + j + 2], w, acc);
            op[u] = acc;
            unsigned int key = __float_as_uint(acc);
            cntAbove += (key >= WHI) ? 1u : 0u;
            bool inwin = (key >= WLO) && (key < WHI);
            unsigned int m = __ballot_sync(0xffffffffu, inwin);
            if (m) {
                int leader = __ffs(m) - 1;
                unsigned int base = 0;
                if (lane == leader) base = atomicAdd(&scnt, (unsigned)__popc(m));
                base = __shfl_sync(0xffffffffu, base, leader);
                if (inwin) {
                    unsigned int pos = base + __popc(m & ((1u << lane) - 1u));
                    if (pos < CAP) mylist[pos] = key - WLO;
                }
            }
        }
        *(float4*)&g_blur[y * HW + c0] = o;

        #pragma unroll
        for (int i = 0; i < 4; i++)
            #pragma unroll
            for (int j = 0; j < 12; j++)
                f[i][j] = f[i + 1][j];
    }

    #pragma unroll
    for (int off = 16; off; off >>= 1)
        cntAbove += __shfl_down_sync(0xffffffffu, cntAbove, off);
    if (lane == 0) sred[threadIdx.x >> 5] = cntAbove;
    __syncthreads();
    if (threadIdx.x == 0) {
        atomicAdd(&g_above[patch], sred[0] + sred[1] + sred[2] + sred[3]);
        unsigned int n = scnt;
        g_listcnt[blk] = (n <= CAP) ? n : CAP;
        if (n > CAP) g_need[patch] = 1;     // overflow -> exact fallback
    }
}

// ---------------- K1b: level-1 histogram from lists (one block per patch) ----------------
__global__ __launch_bounds__(256) void hist_from_list() {
    __shared__ unsigned int h[NW1];
    const int p = blockIdx.x, t = threadIdx.x;
    for (int i = t; i < NW1; i += 256) h[i] = 0u;
    __syncthreads();
    const int pr = p >> 3, pc = p & 7;
    for (int s = 0; s < 16; s++) {                // 16 blur blocks per patch
        const int blk = (pr * 16 + s) * 8 + pc;
        const unsigned int n = g_listcnt[blk];
        const unsigned int* lst = g_listblk + blk * CAP;
        for (unsigned int i = t; i < n; i += 256)
            atomicAdd(&h[lst[i] >> W1SHIFT], 1u);
    }
    __syncthreads();
    for (int i = t; i < NW1; i += 256) g_whist[p][i] = h[i];
}

// ---------------- K2: locate level-1 bin for each quantile; verify window ----------------
__global__ __launch_bounds__(1024) void coarse_select_win() {
    __shared__ unsigned int ss[1024];
    const int p = blockIdx.x, t = threadIdx.x;
    unsigned int c = (t < NW1) ? g_whist[p][t] : 0u;
    ss[t] = c;
    __syncthreads();
    for (int off = 1; off < 1024; off <<= 1) {   // inclusive suffix scan
        unsigned int v = (t + off < 1024) ? ss[t + off] : 0u;
        __syncthreads();
        ss[t] += v;
        __syncthreads();
    }
    const unsigned int ga = g_above[p];
    const unsigned int total_in = ss[0];
    unsigned int above = ((t < 1023) ? ss[t + 1] : 0u) + ga;

    if (t == 0) {
        if ((ga >= K2) || (ga + total_in < K1)) g_need[p] = 1;  // OR (keep overflow flag)
    }

    if (above < K1 && K1 <= above + c) { g_sel[p][0] = (unsigned)t; g_sel[p][1] = above; }
    if (above < K2 && K2 <= above + c) { g_sel[p][2] = (unsigned)t; g_sel[p][3] = above; }
}

// ---------------- K3a: sub-histogram from lists ----------------
__global__ __launch_bounds__(256) void refine_list() {
    const int blk = blockIdx.x;
    const int p = ((blk >> 3) >> 4) * 8 + (blk & 7);
    const unsigned int bin1 = g_sel[p][0], bin2 = g_sel[p][2];
    const unsigned int n = g_listcnt[blk];
    const unsigned int* lst = g_listblk + blk * CAP;
    for (unsigned int i = threadIdx.x; i < n; i += 256) {
        unsigned int wk = lst[i], bin = wk >> W1SHIFT;
        if (bin == bin1) atomicAdd(&g_sub[p][0][wk & 1023u], 1u);
        if (bin == bin2) atomicAdd(&g_sub[p][1][wk & 1023u], 1u);
    }
}

// ---------------- K3b: exact float-bit key within the level-1 bin ----------------
__global__ __launch_bounds__(1024) void refine_select() {
    __shared__ unsigned int ss[1024];
    const int p = blockIdx.x, t = threadIdx.x;
    if (g_need[p]) return;

    for (int q = 0; q < 2; q++) {
        const unsigned int bin = g_sel[p][q * 2];
        const unsigned int ab  = g_sel[p][q * 2 + 1];
        const unsigned int r   = (q ? K2 : K1) - ab;

        unsigned int c = g_sub[p][q][t];
        ss[t] = c;
        __syncthreads();
        for (int off = 1; off < 1024; off <<= 1) {
            unsigned int v = (t + off < 1024) ? ss[t + off] : 0u;
            __syncthreads();
            ss[t] += v;
            __syncthreads();
        }
        unsigned int above = (t < 1023) ? ss[t + 1] : 0u;
        if (t == 0) g_key[p][q] = WLO + (bin << W1SHIFT);
        __syncthreads();
        if (above < r && r <= above + c)
            g_key[p][q] = WLO + (bin << W1SHIFT) + (unsigned)t;
        __syncthreads();
    }
}

// ---------------- K3c: gated exact fallback (binary search on key) ----------------
__global__ __launch_bounds__(1024) void fb_exact() {
    const int p = blockIdx.x;
    if (!g_need[p]) return;
    __shared__ unsigned int sred[32];
    __shared__ unsigned int scnt2;
    const float* base = g_blur + ((p >> 3) * 512) * HW + (p & 7) * 512;
    const int t = threadIdx.x, lane = t & 31, wid = t >> 5;

    for (int q = 0; q < 2; q++) {
        const unsigned int K = q ? K2 : K1;
        unsigned int lo = 0u, hi = 0x40000000u;
        while (hi - lo > 1u) {
            unsigned int mid = lo + ((hi - lo) >> 1);
            unsigned int cnt = 0;
            for (int i = t; i < 512 * 512; i += 1024) {
                unsigned int key = __float_as_uint(base[(i >> 9) * HW + (i & 511)]);
                cnt += (key >= mid) ? 1u : 0u;
            }
            #pragma unroll
            for (int off = 16; off; off >>= 1)
                cnt += __shfl_down_sync(0xffffffffu, cnt, off);
            if (lane == 0) sred[wid] = cnt;
            __syncthreads();
            if (t == 0) {
                unsigned int s = 0;
                for (int i = 0; i < 32; i++) s += sred[i];
                scnt2 = s;
            }
            __syncthreads();
            if (scnt2 >= K) lo = mid; else hi = mid;
            __syncthreads();
        }
        if (t == 0) g_key[p][q] = lo;
        __syncthreads();
    }
}

// ---------------- K4: sequential threshold walk (bit-faithful, unrolled chain) ----------------
// Same fp operations/comparisons as the reference loops; only control flow is
// restructured (16 dependent steps computed per branch round).
__device__ __forceinline__ float walk_down(float th, float A) {
    for (int g = 0; g < 20000; g++) {
        if (!(A <= th)) return th;
        float t1  = th  - 0.0005f; if (A > t1)  return t1;
        float t2  = t1  - 0.0005f; if (A > t2)  return t2;
        float t3  = t2  - 0.0005f; if (A > t3)  return t3;
        float t4  = t3  - 0.0005f; if (A > t4)  return t4;
        float t5  = t4  - 0.0005f; if (A > t5)  return t5;
        float t6  = t5  - 0.0005f; if (A > t6)  return t6;
        float t7  = t6  - 0.0005f; if (A > t7)  return t7;
        float t8  = t7  - 0.0005f; if (A > t8)  return t8;
        float t9  = t8  - 0.0005f; if (A > t9)  return t9;
        float t10 = t9  - 0.0005f; if (A > t10) return t10;
        float t11 = t10 - 0.0005f; if (A > t11) return t11;
        float t12 = t11 - 0.0005f; if (A > t12) return t12;
        float t13 = t12 - 0.0005f; if (A > t13) return t13;
        float t14 = t13 - 0.0005f; if (A > t14) return t14;
        float t15 = t14 - 0.0005f; if (A > t15) return t15;
        th = t15 - 0.0005f;
    }
    return th;
}
__device__ __forceinline__ float walk_up(float th, float B) {
    for (int g = 0; g < 20000; g++) {
        if (!(B > th)) return th;
        float t1  = th  + 0.0005f; if (B <= t1)  return t1;
        float t2  = t1  + 0.0005f; if (B <= t2)  return t2;
        float t3  = t2  + 0.0005f; if (B <= t3)  return t3;
        float t4  = t3  + 0.0005f; if (B <= t4)  return t4;
        float t5  = t4  + 0.0005f; if (B <= t5)  return t5;
        float t6  = t5  + 0.0005f; if (B <= t6)  return t6;
        float t7  = t6  + 0.0005f; if (B <= t7)  return t7;
        float t8  = t7  + 0.0005f; if (B <= t8)  return t8;
        float t9  = t8  + 0.0005f; if (B <= t9)  return t9;
        float t10 = t9  + 0.0005f; if (B <= t10) return t10;
        float t11 = t10 + 0.0005f; if (B <= t11) return t11;
        float t12 = t11 + 0.0005f; if (B <= t12) return t12;
        float t13 = t12 + 0.0005f; if (B <= t13) return t13;
        float t14 = t13 + 0.0005f; if (B <= t14) return t14;
        float t15 = t14 + 0.0005f; if (B <= t15) return t15;
        th = t15 + 0.0005f;
    }
    return th;
}

__global__ void walk() {
    if (blockIdx.x == 0 && threadIdx.x == 0) {
        float th = 0.5f;
        for (int p = 0; p < NPATCH; p++) {
            float A = __uint_as_float(g_key[p][0]);
            float B = __uint_as_float(g_key[p][1]);
            th = walk_down(th, A);
            th = walk_up(th, B);
            g_th[p] = th;
        }
    }
}

// ---------------- K5: bit-packed binarize + close (dilate5, erode5) ----------------
#define CTW  256
#define CTH  128
#define WPR  10
#define TROWS 136
__global__ __launch_bounds__(256) void close_k(float* __restrict__ out) {
    __shared__ unsigned int A[TROWS][WPR];
    __shared__ unsigned int B[TROWS][WPR];
    __shared__ float sth[NPATCH];
    const int t = threadIdx.x;
    if (t < NPATCH) sth[t] = g_th[t];
    __syncthreads();

    const int gx0 = blockIdx.x * CTW;
    const int gy0 = blockIdx.y * CTH;
    const int lane = t & 31, wid = t >> 5;

    for (int idx = wid; idx < TROWS * WPR; idx += 8) {
        int r = idx / WPR, wc = idx % WPR;
        int gy = gy0 + r - 4;
        int gx = gx0 + (wc - 1) * 32 + lane;
        unsigned int bit = 0;
        if ((unsigned)gy < HW && (unsigned)gx < HW) {
            float bl = g_blur[gy * HW + gx];
            bit = (bl > sth[((gy >> 9) << 3) + (gx >> 9)]) ? 1u : 0u;
        }
        unsigned int word = __ballot_sync(0xffffffffu, bit);
        if (lane == 0) A[r][wc] = word;
    }
    __syncthreads();

    for (int i = t; i < TROWS * WPR; i += 256) {
        int r = i / WPR, wc = i % WPR;
        unsigned int wv = A[r][wc];
        unsigned int lw = wc > 0       ? A[r][wc - 1] : 0u;
        unsigned int rw = wc < WPR - 1 ? A[r][wc + 1] : 0u;
        B[r][wc] = wv | __funnelshift_r(wv, rw, 1) | __funnelshift_r(wv, rw, 2)
                      | __funnelshift_l(lw, wv, 1) | __funnelshift_l(lw, wv, 2);
    }
    __syncthreads();

    for (int i = t; i < TROWS * WPR; i += 256) {
        int r = i / WPR, wc = i % WPR;
        unsigned int d = 0u;
        if (r >= 2 && r < TROWS - 2)
            d = B[r-2][wc] | B[r-1][wc] | B[r][wc] | B[r+1][wc] | B[r+2][wc];
        int gy = gy0 + r - 4;
        bool xout = (wc == 0 && gx0 == 0) || (wc == WPR - 1 && gx0 + CTW == HW);
        if ((unsigned)gy >= HW || xout) d = 0xffffffffu;
        A[r][wc] = d;
    }
    __syncthreads();

    for (int i = t; i < TROWS * WPR; i += 256) {
        int r = i / WPR, wc = i % WPR;
        unsigned int wv = A[r][wc];
        unsigned int lw = wc > 0       ? A[r][wc - 1] : 0xffffffffu;
        unsigned int rw = wc < WPR - 1 ? A[r][wc + 1] : 0xffffffffu;
        B[r][wc] = wv & __funnelshift_r(wv, rw, 1) & __funnelshift_r(wv, rw, 2)
                      & __funnelshift_l(lw, wv, 1) & __funnelshift_l(lw, wv, 2);
    }
    __syncthreads();

    for (int i = t; i < CTH * 8; i += 256) {
        int r = (i >> 3) + 4, wc = (i & 7) + 1;
        unsigned int v = B[r-2][wc] & B[r-1][wc] & B[r][wc] & B[r+1][wc] & B[r+2][wc];
        int gy = gy0 + r - 4;
        int gx = gx0 + (wc - 1) * 32;
        float4* o = (float4*)&out[gy * HW + gx];
        #pragma unroll
        for (int q = 0; q < 8; q++) {
            float4 fv;
            fv.x = (v >> (q * 4 + 0)) & 1u ? 1.0f : 0.0f;
            fv.y = (v >> (q * 4 + 1)) & 1u ? 1.0f : 0.0f;
            fv.z = (v >> (q * 4 + 2)) & 1u ? 1.0f : 0.0f;
            fv.w = (v >> (q * 4 + 3)) & 1u ? 1.0f : 0.0f;
            o[q] = fv;
        }
    }
}

// ---------------- launch ----------------
extern "C" void kernel_launch(void* const* d_in, const int* in_sizes, int n_in,
                              void* d_out, int out_size) {
    const float* x  = (const float*)d_in[0];
    const float* bk = (const float*)d_in[1];
    float* out = (float*)d_out;
    (void)in_sizes; (void)n_in; (void)out_size;

    zero_k<<<(NPATCH * 2 * 1024 + 255) / 256, 256>>>();
    dummy_k<<<1, 32>>>();
    dummy_k<<<1, 32>>>();                       // keeps ncu slot on blur_hist
    blur_hist<<<dim3(HW / 512, HW / RPB), 128>>>(x, bk);
    hist_from_list<<<NPATCH, 256>>>();
    coarse_select_win<<<NPATCH, 1024>>>();
    refine_list<<<NBLK, 256>>>();
    refine_select<<<NPATCH, 1024>>>();
    fb_exact<<<NPATCH, 1024>>>();
    walk<<<1, 32>>>();
    close_k<<<dim3(HW / CTW, HW / CTH), 256>>>(out);
}

// round 10
// speedup vs baseline: 1.2405x; 1.2320x over previous
#include <cuda_runtime.h>

// ---------------- problem constants ----------------
#define HW      4096
#define NPIX    (HW*HW)
#define NPATCH  64
#define K1      31458u   // loop1 continues iff count(v>th) <= 31457  <=>  v_(31458) <= th
#define K2      20972u   // loop2 continues iff count(v>th) >= 20972  <=>  v_(20972) >  th

// value window (verified per-patch; exact fallback if violated)
#define WLO     0x3F0E0000u   // ~0.5547
#define WHI     0x3F1A0000u   // ~0.6016
#define NW1     768           // level-1 bins of 1024 keys each
#define W1SHIFT 10

#define RPB     32            // rows per blur block

// ---------------- device scratch ----------------
__device__ float        g_blur[NPIX];
__device__ unsigned int g_whist[NPATCH][NW1];
__device__ unsigned int g_above[NPATCH];         // count(key >= WHI)
__device__ int          g_need [NPATCH];         // exact-fallback flag
__device__ unsigned int g_sub  [NPATCH][2][1024];
__device__ unsigned int g_sel  [NPATCH][4];      // bin1, above1, bin2, above2
__device__ unsigned int g_key  [NPATCH][2];
__device__ float        g_th   [NPATCH];

// ---------------- K0: zero scratch ----------------
__global__ void zero_k() {
    int i = blockIdx.x * 256 + threadIdx.x;
    if (i < NPATCH * NW1)      ((unsigned int*)g_whist)[i] = 0u;
    if (i < NPATCH * 2 * 1024) ((unsigned int*)g_sub)[i]   = 0u;
    if (i < NPATCH) { g_above[i] = 0u; g_need[i] = 0; }
}

// ---------------- dummy: keeps ncu capture slot (launch #4) on blur_hist ----------------
__global__ void dummy_k() {
    if ((int)threadIdx.x >= 1 << 20) g_need[0] = 0;   // never executes
}

// ---------------- K1: blur (rolling window, 3 LDG.128/row) + windowed smem hist ----------
// 128 threads x 4 cols = 512 cols (one patch width), RPB rows per block.
// Per-pixel 25-tap fmaf chain IDENTICAL to the passing version (kw outer, kh inner).
__device__ __forceinline__ void load_row(float* dst, const float* __restrict__ x,
                                         int yy, int c0, bool safe) {
    if (yy < 0 || yy >= HW) {
        #pragma unroll
        for (int j = 0; j < 12; j++) dst[j] = 0.0f;
    } else if (safe) {
        const float4* p = (const float4*)&x[yy * HW + c0 - 4];
        float4 a = __ldg(p), b = __ldg(p + 1), c = __ldg(p + 2);
        dst[0]=a.x; dst[1]=a.y; dst[2]=a.z;  dst[3]=a.w;
        dst[4]=b.x; dst[5]=b.y; dst[6]=b.z;  dst[7]=b.w;
        dst[8]=c.x; dst[9]=c.y; dst[10]=c.z; dst[11]=c.w;
    } else {
        #pragma unroll
        for (int j = 0; j < 12; j++) {
            int cc = c0 - 4 + j;
            dst[j] = (cc >= 0 && cc < HW) ? __ldg(&x[yy * HW + cc]) : 0.0f;
        }
    }
}

__global__ __launch_bounds__(128) void blur_hist(const float* __restrict__ x,
                                                 const float* __restrict__ bk) {
    __shared__ unsigned int wh[NW1];
    __shared__ unsigned int sred[4];
    for (int i = threadIdx.x; i < NW1; i += 128) wh[i] = 0u;
    __syncthreads();

    const float w  = bk[0];
    const int   c0 = blockIdx.x * 512 + threadIdx.x * 4;
    const int   y0 = blockIdx.y * RPB;
    const int   patch = ((y0 >> 9) << 3) + (c0 >> 9);
    const bool  safe = (c0 >= 4) && (c0 <= HW - 9);
    const int   lane = threadIdx.x & 31;
    unsigned int cntAbove = 0;

    float f[5][12];
    #pragma unroll
    for (int i = 0; i < 4; i++) load_row(f[i], x, y0 - 2 + i, c0, safe);

    for (int y = y0; y < y0 + RPB; y++) {
        load_row(f[4], x, y + 2, c0, safe);

        float4 o;
        float* op = (float*)&o;
        #pragma unroll
        for (int u = 0; u < 4; u++) {
            float acc = 0.0f;
            #pragma unroll
            for (int j = 0; j < 5; j++)        // kw outer
                #pragma unroll
                for (int i = 0; i < 5; i++)    // kh inner (fastest) — Eigen order
                    acc = fmaf(f[i][u + j + 2], w, acc);
            op[u] = acc;
            unsigned int key = __float_as_uint(acc);
            cntAbove += (key >= WHI) ? 1u : 0u;
            if (key >= WLO && key < WHI)
                atomicAdd(&wh[(key - WLO) >> W1SHIFT], 1u);
        }
        *(float4*)&g_blur[y * HW + c0] = o;

        #pragma unroll
        for (int i = 0; i < 4; i++)
            #pragma unroll
            for (int j = 0; j < 12; j++)
                f[i][j] = f[i + 1][j];
    }

    #pragma unroll
    for (int off = 16; off; off >>= 1)
        cntAbove += __shfl_down_sync(0xffffffffu, cntAbove, off);
    if (lane == 0) sred[threadIdx.x >> 5] = cntAbove;
    __syncthreads();
    if (threadIdx.x == 0)
        atomicAdd(&g_above[patch], sred[0] + sred[1] + sred[2] + sred[3]);
    for (int i = threadIdx.x; i < NW1; i += 128) {
        unsigned int v = wh[i];
        if (v) atomicAdd(&g_whist[patch][i], v);
    }
}

// ---------------- K2: locate level-1 bin for each quantile; verify window ----------------
__global__ __launch_bounds__(1024) void coarse_select_win() {
    __shared__ unsigned int ss[1024];
    const int p = blockIdx.x, t = threadIdx.x;
    unsigned int c = (t < NW1) ? g_whist[p][t] : 0u;
    ss[t] = c;
    __syncthreads();
    for (int off = 1; off < 1024; off <<= 1) {   // inclusive suffix scan
        unsigned int v = (t + off < 1024) ? ss[t + off] : 0u;
        __syncthreads();
        ss[t] += v;
        __syncthreads();
    }
    const unsigned int ga = g_above[p];
    const unsigned int total_in = ss[0];
    unsigned int above = ((t < 1023) ? ss[t + 1] : 0u) + ga;

    if (t == 0)
        g_need[p] = (ga >= K2) || (ga + total_in < K1) ? 1 : 0;

    if (above < K1 && K1 <= above + c) { g_sel[p][0] = (unsigned)t; g_sel[p][1] = above; }
    if (above < K2 && K2 <= above + c) { g_sel[p][2] = (unsigned)t; g_sel[p][3] = above; }
}

// ---------------- K3a: sub-histogram, full re-read of g_blur (float4, grid-stride) ----------------
__global__ __launch_bounds__(256) void refine_pass() {
    __shared__ unsigned int sbin[NPATCH][2];
    if (threadIdx.x < NPATCH) {
        sbin[threadIdx.x][0] = g_sel[threadIdx.x][0];
        sbin[threadIdx.x][1] = g_sel[threadIdx.x][2];
    }
    __syncthreads();
    const float4* b4 = (const float4*)g_blur;
    const unsigned int n4 = NPIX / 4;
    for (unsigned int i = blockIdx.x * 256 + threadIdx.x; i < n4;
         i += gridDim.x * 256) {
        float4 v = __ldg(&b4[i]);
        int y = i >> 10;
        int p = ((y >> 9) << 3) + ((i & 1023u) >> 7);
        const float* vp = (const float*)&v;
        #pragma unroll
        for (int u = 0; u < 4; u++) {
            unsigned int key = __float_as_uint(vp[u]);
            if (key >= WLO && key < WHI) {
                unsigned int wk  = key - WLO;
                unsigned int bin = wk >> W1SHIFT;
                if (bin == sbin[p][0]) atomicAdd(&g_sub[p][0][wk & 1023u], 1u);
                if (bin == sbin[p][1]) atomicAdd(&g_sub[p][1][wk & 1023u], 1u);
            }
        }
    }
}

// ---------------- K3b: exact float-bit key within the level-1 bin ----------------
__global__ __launch_bounds__(1024) void refine_select() {
    __shared__ unsigned int ss[1024];
    const int p = blockIdx.x, t = threadIdx.x;
    if (g_need[p]) return;

    for (int q = 0; q < 2; q++) {
        const unsigned int bin = g_sel[p][q * 2];
        const unsigned int ab  = g_sel[p][q * 2 + 1];
        const unsigned int r   = (q ? K2 : K1) - ab;

        unsigned int c = g_sub[p][q][t];
        ss[t] = c;
        __syncthreads();
        for (int off = 1; off < 1024; off <<= 1) {
            unsigned int v = (t + off < 1024) ? ss[t + off] : 0u;
            __syncthreads();
            ss[t] += v;
            __syncthreads();
        }
        unsigned int above = (t < 1023) ? ss[t + 1] : 0u;
        if (t == 0) g_key[p][q] = WLO + (bin << W1SHIFT);
        __syncthreads();
        if (above < r && r <= above + c)
            g_key[p][q] = WLO + (bin << W1SHIFT) + (unsigned)t;
        __syncthreads();
    }
}

// ---------------- K3c: gated exact fallback (binary search on key) ----------------
__global__ __launch_bounds__(1024) void fb_exact() {
    const int p = blockIdx.x;
    if (!g_need[p]) return;
    __shared__ unsigned int sred[32];
    __shared__ unsigned int scnt;
    const float* base = g_blur + ((p >> 3) * 512) * HW + (p & 7) * 512;
    const int t = threadIdx.x, lane = t & 31, wid = t >> 5;

    for (int q = 0; q < 2; q++) {
        const unsigned int K = q ? K2 : K1;
        unsigned int lo = 0u, hi = 0x40000000u;
        while (hi - lo > 1u) {
            unsigned int mid = lo + ((hi - lo) >> 1);
            unsigned int cnt = 0;
            for (int i = t; i < 512 * 512; i += 1024) {
                unsigned int key = __float_as_uint(base[(i >> 9) * HW + (i & 511)]);
                cnt += (key >= mid) ? 1u : 0u;
            }
            #pragma unroll
            for (int off = 16; off; off >>= 1)
                cnt += __shfl_down_sync(0xffffffffu, cnt, off);
            if (lane == 0) sred[wid] = cnt;
            __syncthreads();
            if (t == 0) {
                unsigned int s = 0;
                for (int i = 0; i < 32; i++) s += sred[i];
                scnt = s;
            }
            __syncthreads();
            if (scnt >= K) lo = mid; else hi = mid;
            __syncthreads();
        }
        if (t == 0) g_key[p][q] = lo;
        __syncthreads();
    }
}

// ---------------- K4: sequential threshold walk (bit-faithful, unrolled chain) ----------------
// Same fp operations/comparisons as the reference loops; only control flow is
// restructured (16 dependent steps computed per branch round).
__device__ __forceinline__ float walk_down(float th, float A) {
    for (int g = 0; g < 20000; g++) {
        if (!(A <= th)) return th;
        float t1  = th  - 0.0005f; if (A > t1)  return t1;
        float t2  = t1  - 0.0005f; if (A > t2)  return t2;
        float t3  = t2  - 0.0005f; if (A > t3)  return t3;
        float t4  = t3  - 0.0005f; if (A > t4)  return t4;
        float t5  = t4  - 0.0005f; if (A > t5)  return t5;
        float t6  = t5  - 0.0005f; if (A > t6)  return t6;
        float t7  = t6  - 0.0005f; if (A > t7)  return t7;
        float t8  = t7  - 0.0005f; if (A > t8)  return t8;
        float t9  = t8  - 0.0005f; if (A > t9)  return t9;
        float t10 = t9  - 0.0005f; if (A > t10) return t10;
        float t11 = t10 - 0.0005f; if (A > t11) return t11;
        float t12 = t11 - 0.0005f; if (A > t12) return t12;
        float t13 = t12 - 0.0005f; if (A > t13) return t13;
        float t14 = t13 - 0.0005f; if (A > t14) return t14;
        float t15 = t14 - 0.0005f; if (A > t15) return t15;
        th = t15 - 0.0005f;
    }
    return th;
}
__device__ __forceinline__ float walk_up(float th, float B) {
    for (int g = 0; g < 20000; g++) {
        if (!(B > th)) return th;
        float t1  = th  + 0.0005f; if (B <= t1)  return t1;
        float t2  = t1  + 0.0005f; if (B <= t2)  return t2;
        float t3  = t2  + 0.0005f; if (B <= t3)  return t3;
        float t4  = t3  + 0.0005f; if (B <= t4)  return t4;
        float t5  = t4  + 0.0005f; if (B <= t5)  return t5;
        float t6  = t5  + 0.0005f; if (B <= t6)  return t6;
        float t7  = t6  + 0.0005f; if (B <= t7)  return t7;
        float t8  = t7  + 0.0005f; if (B <= t8)  return t8;
        float t9  = t8  + 0.0005f; if (B <= t9)  return t9;
        float t10 = t9  + 0.0005f; if (B <= t10) return t10;
        float t11 = t10 + 0.0005f; if (B <= t11) return t11;
        float t12 = t11 + 0.0005f; if (B <= t12) return t12;
        float t13 = t12 + 0.0005f; if (B <= t13) return t13;
        float t14 = t13 + 0.0005f; if (B <= t14) return t14;
        float t15 = t14 + 0.0005f; if (B <= t15) return t15;
        th = t15 + 0.0005f;
    }
    return th;
}

__global__ void walk() {
    if (blockIdx.x == 0 && threadIdx.x == 0) {
        float th = 0.5f;
        for (int p = 0; p < NPATCH; p++) {
            float A = __uint_as_float(g_key[p][0]);
            float B = __uint_as_float(g_key[p][1]);
            th = walk_down(th, A);
            th = walk_up(th, B);
            g_th[p] = th;
        }
    }
}

// ---------------- K5: bit-packed binarize + close (dilate5, erode5) ----------------
#define CTW  256
#define CTH  128
#define WPR  10
#define TROWS 136
__global__ __launch_bounds__(256) void close_k(float* __restrict__ out) {
    __shared__ unsigned int A[TROWS][WPR];
    __shared__ unsigned int B[TROWS][WPR];
    __shared__ float sth[NPATCH];
    const int t = threadIdx.x;
    if (t < NPATCH) sth[t] = g_th[t];
    __syncthreads();

    const int gx0 = blockIdx.x * CTW;
    const int gy0 = blockIdx.y * CTH;
    const int lane = t & 31, wid = t >> 5;

    for (int idx = wid; idx < TROWS * WPR; idx += 8) {
        int r = idx / WPR, wc = idx % WPR;
        int gy = gy0 + r - 4;
        int gx = gx0 + (wc - 1) * 32 + lane;
        unsigned int bit = 0;
        if ((unsigned)gy < HW && (unsigned)gx < HW) {
            float bl = g_blur[gy * HW + gx];
            bit = (bl > sth[((gy >> 9) << 3) + (gx >> 9)]) ? 1u : 0u;
        }
        unsigned int word = __ballot_sync(0xffffffffu, bit);
        if (lane == 0) A[r][wc] = word;
    }
    __syncthreads();

    for (int i = t; i < TROWS * WPR; i += 256) {
        int r = i / WPR, wc = i % WPR;
        unsigned int wv = A[r][wc];
        unsigned int lw = wc > 0       ? A[r][wc - 1] : 0u;
        unsigned int rw = wc < WPR - 1 ? A[r][wc + 1] : 0u;
        B[r][wc] = wv | __funnelshift_r(wv, rw, 1) | __funnelshift_r(wv, rw, 2)
                      | __funnelshift_l(lw, wv, 1) | __funnelshift_l(lw, wv, 2);
    }
    __syncthreads();

    for (int i = t; i < TROWS * WPR; i += 256) {
        int r = i / WPR, wc = i % WPR;
        unsigned int d = 0u;
        if (r >= 2 && r < TROWS - 2)
            d = B[r-2][wc] | B[r-1][wc] | B[r][wc] | B[r+1][wc] | B[r+2][wc];
        int gy = gy0 + r - 4;
        bool xout = (wc == 0 && gx0 == 0) || (wc == WPR - 1 && gx0 + CTW == HW);
        if ((unsigned)gy >= HW || xout) d = 0xffffffffu;
        A[r][wc] = d;
    }
    __syncthreads();

    for (int i = t; i < TROWS * WPR; i += 256) {
        int r = i / WPR, wc = i % WPR;
        unsigned int wv = A[r][wc];
        unsigned int lw = wc > 0       ? A[r][wc - 1] : 0xffffffffu;
        unsigned int rw = wc < WPR - 1 ? A[r][wc + 1] : 0xffffffffu;
        B[r][wc] = wv & __funnelshift_r(wv, rw, 1) & __funnelshift_r(wv, rw, 2)
                      & __funnelshift_l(lw, wv, 1) & __funnelshift_l(lw, wv, 2);
    }
    __syncthreads();

    for (int i = t; i < CTH * 8; i += 256) {
        int r = (i >> 3) + 4, wc = (i & 7) + 1;
        unsigned int v = B[r-2][wc] & B[r-1][wc] & B[r][wc] & B[r+1][wc] & B[r+2][wc];
        int gy = gy0 + r - 4;
        int gx = gx0 + (wc - 1) * 32;
        float4* o = (float4*)&out[gy * HW + gx];
        #pragma unroll
        for (int q = 0; q < 8; q++) {
            float4 fv;
            fv.x = (v >> (q * 4 + 0)) & 1u ? 1.0f : 0.0f;
            fv.y = (v >> (q * 4 + 1)) & 1u ? 1.0f : 0.0f;
            fv.z = (v >> (q * 4 + 2)) & 1u ? 1.0f : 0.0f;
            fv.w = (v >> (q * 4 + 3)) & 1u ? 1.0f : 0.0f;
            o[q] = fv;
        }
    }
}

// ---------------- launch ----------------
extern "C" void kernel_launch(void* const* d_in, const int* in_sizes, int n_in,
                              void* d_out, int out_size) {
    const float* x  = (const float*)d_in[0];
    const float* bk = (const float*)d_in[1];
    float* out = (float*)d_out;
    (void)in_sizes; (void)n_in; (void)out_size;

    zero_k<<<(NPATCH * 2 * 1024 + 255) / 256, 256>>>();
    dummy_k<<<1, 32>>>();
    dummy_k<<<1, 32>>>();                       // keeps ncu slot on blur_hist
    blur_hist<<<dim3(HW / 512, HW / RPB), 128>>>(x, bk);
    coarse_select_win<<<NPATCH, 1024>>>();
    refine_pass<<<2048, 256>>>();
    refine_select<<<NPATCH, 1024>>>();
    fb_exact<<<NPATCH, 1024>>>();
    walk<<<1, 32>>>();
    close_k<<<dim3(HW / CTW, HW / CTH), 256>>>(out);
}

// round 11
// speedup vs baseline: 1.2434x; 1.0023x over previous
#include <cuda_runtime.h>

// ---------------- problem constants ----------------
#define HW      4096
#define NPIX    (HW*HW)
#define NPATCH  64
#define K1      31458u   // loop1 continues iff count(v>th) <= 31457  <=>  v_(31458) <= th
#define K2      20972u   // loop2 continues iff count(v>th) >= 20972  <=>  v_(20972) >  th

// value window (verified per-patch; exact fallback if violated)
#define WLO     0x3F0E0000u   // ~0.5547
#define WHI     0x3F1A0000u   // ~0.6016
#define NW1     768           // level-1 bins of 1024 keys each
#define W1SHIFT 10

#define RPB     16            // rows per blur block
#define BPPY    (512 / RPB)   // blur blocks per patch, vertically (32)
#define NBLK    (8 * (HW / RPB))   // total blur blocks (2048)

// ---------------- device scratch ----------------
__device__ float        g_blur[NPIX];
__device__ unsigned int g_bhist[NBLK][NW1];      // per-block hist (plain stores, no zeroing)
__device__ unsigned int g_babove[NBLK];
__device__ int          g_need [NPATCH];         // exact-fallback flag (plain store)
__device__ unsigned int g_sub  [NPATCH][2][1024];
__device__ unsigned int g_sel  [NPATCH][4];      // bin1, above1, bin2, above2
__device__ unsigned int g_key  [NPATCH][2];
__device__ float        g_th   [NPATCH];

// ---------------- K1: blur (rolling window, 3 LDG.128/row) + per-block windowed hist ------
// 128 threads x 4 cols = 512 cols (one patch width), RPB rows per block.
// Per-pixel 25-tap fmaf chain IDENTICAL to the passing version (kw outer, kh inner).
__device__ __forceinline__ void load_row(float* dst, const float* __restrict__ x,
                                         int yy, int c0, bool safe) {
    if (yy < 0 || yy >= HW) {
        #pragma unroll
        for (int j = 0; j < 12; j++) dst[j] = 0.0f;
    } else if (safe) {
        const float4* p = (const float4*)&x[yy * HW + c0 - 4];
        float4 a = __ldg(p), b = __ldg(p + 1), c = __ldg(p + 2);
        dst[0]=a.x; dst[1]=a.y; dst[2]=a.z;  dst[3]=a.w;
        dst[4]=b.x; dst[5]=b.y; dst[6]=b.z;  dst[7]=b.w;
        dst[8]=c.x; dst[9]=c.y; dst[10]=c.z; dst[11]=c.w;
    } else {
        #pragma unroll
        for (int j = 0; j < 12; j++) {
            int cc = c0 - 4 + j;
            dst[j] = (cc >= 0 && cc < HW) ? __ldg(&x[yy * HW + cc]) : 0.0f;
        }
    }
}

__global__ __launch_bounds__(128) void blur_hist(const float* __restrict__ x,
                                                 const float* __restrict__ bk) {
    __shared__ unsigned int wh[NW1];
    __shared__ unsigned int sred[4];
    for (int i = threadIdx.x; i < NW1; i += 128) wh[i] = 0u;
    __syncthreads();

    const float w  = bk[0];
    const int   c0 = blockIdx.x * 512 + threadIdx.x * 4;
    const int   y0 = blockIdx.y * RPB;
    const int   blk = blockIdx.y * 8 + blockIdx.x;
    const bool  safe = (c0 >= 4) && (c0 <= HW - 9);
    const int   lane = threadIdx.x & 31;
    unsigned int cntAbove = 0;

    float f[5][12];
    #pragma unroll
    for (int i = 0; i < 4; i++) load_row(f[i], x, y0 - 2 + i, c0, safe);

    for (int y = y0; y < y0 + RPB; y++) {
        load_row(f[4], x, y + 2, c0, safe);

        float4 o;
        float* op = (float*)&o;
        #pragma unroll
        for (int u = 0; u < 4; u++) {
            float acc = 0.0f;
            #pragma unroll
            for (int j = 0; j < 5; j++)        // kw outer
                #pragma unroll
                for (int i = 0; i < 5; i++)    // kh inner (fastest) — Eigen order
                    acc = fmaf(f[i][u + j + 2], w, acc);
            op[u] = acc;
            unsigned int key = __float_as_uint(acc);
            cntAbove += (key >= WHI) ? 1u : 0u;
            if (key >= WLO && key < WHI)
                atomicAdd(&wh[(key - WLO) >> W1SHIFT], 1u);
        }
        *(float4*)&g_blur[y * HW + c0] = o;

        #pragma unroll
        for (int i = 0; i < 4; i++)
            #pragma unroll
            for (int j = 0; j < 12; j++)
                f[i][j] = f[i + 1][j];
    }

    #pragma unroll
    for (int off = 16; off; off >>= 1)
        cntAbove += __shfl_down_sync(0xffffffffu, cntAbove, off);
    if (lane == 0) sred[threadIdx.x >> 5] = cntAbove;
    __syncthreads();
    if (threadIdx.x == 0)
        g_babove[blk] = sred[0] + sred[1] + sred[2] + sred[3];
    for (int i = threadIdx.x; i < NW1; i += 128)
        g_bhist[blk][i] = wh[i];
}

// ---------------- K2: sum block hists, locate level-1 bins, zero g_sub ----------------
__global__ __launch_bounds__(1024) void coarse_select_win() {
    __shared__ unsigned int ss[1024];
    __shared__ unsigned int sga;
    const int p = blockIdx.x, t = threadIdx.x;
    const int pr = p >> 3, pc = p & 7;

    // zero the sub-hist for this patch (replaces zero_k; runs before refine_pass)
    g_sub[p][0][t] = 0u;
    g_sub[p][1][t] = 0u;

    // sum the per-block above-counts (BPPY = 32 -> one warp)
    if (t < BPPY) {
        unsigned int a = g_babove[(pr * BPPY + t) * 8 + pc];
        #pragma unroll
        for (int off = 16; off; off >>= 1)
            a += __shfl_down_sync(0xffffffffu, a, off);
        if (t == 0) sga = a;
    }

    // sum the per-block hists
    unsigned int c = 0;
    if (t < NW1) {
        #pragma unroll 4
        for (int s = 0; s < BPPY; s++)
            c += g_bhist[(pr * BPPY + s) * 8 + pc][t];
    }
    ss[t] = c;
    __syncthreads();
    for (int off = 1; off < 1024; off <<= 1) {   // inclusive suffix scan
        unsigned int v = (t + off < 1024) ? ss[t + off] : 0u;
        __syncthreads();
        ss[t] += v;
        __syncthreads();
    }
    const unsigned int ga = sga;
    const unsigned int total_in = ss[0];
    unsigned int above = ((t < 1023) ? ss[t + 1] : 0u) + ga;

    if (t == 0)
        g_need[p] = (ga >= K2) || (ga + total_in < K1) ? 1 : 0;

    if (above < K1 && K1 <= above + c) { g_sel[p][0] = (unsigned)t; g_sel[p][1] = above; }
    if (above < K2 && K2 <= above + c) { g_sel[p][2] = (unsigned)t; g_sel[p][3] = above; }
}

// ---------------- K3a: sub-histogram, full re-read of g_blur (float4, grid-stride) ----------------
__global__ __launch_bounds__(256) void refine_pass() {
    __shared__ unsigned int sbin[NPATCH][2];
    if (threadIdx.x < NPATCH) {
        sbin[threadIdx.x][0] = g_sel[threadIdx.x][0];
        sbin[threadIdx.x][1] = g_sel[threadIdx.x][2];
    }
    __syncthreads();
    const float4* b4 = (const float4*)g_blur;
    const unsigned int n4 = NPIX / 4;
    for (unsigned int i = blockIdx.x * 256 + threadIdx.x; i < n4;
         i += gridDim.x * 256) {
        float4 v = __ldg(&b4[i]);
        int y = i >> 10;
        int p = ((y >> 9) << 3) + ((i & 1023u) >> 7);
        const float* vp = (const float*)&v;
        #pragma unroll
        for (int u = 0; u < 4; u++) {
            unsigned int key = __float_as_uint(vp[u]);
            if (key >= WLO && key < WHI) {
                unsigned int wk  = key - WLO;
                unsigned int bin = wk >> W1SHIFT;
                if (bin == sbin[p][0]) atomicAdd(&g_sub[p][0][wk & 1023u], 1u);
                if (bin == sbin[p][1]) atomicAdd(&g_sub[p][1][wk & 1023u], 1u);
            }
        }
    }
}

// ---------------- K3b: exact key within level-1 bin, with merged exact fallback ---------------
__global__ __launch_bounds__(1024) void refine_select_fb() {
    __shared__ unsigned int ss[1024];
    __shared__ unsigned int scnt;
    const int p = blockIdx.x, t = threadIdx.x;
    const int lane = t & 31, wid = t >> 5;

    if (!g_need[p]) {
        for (int q = 0; q < 2; q++) {
            const unsigned int bin = g_sel[p][q * 2];
            const unsigned int ab  = g_sel[p][q * 2 + 1];
            const unsigned int r   = (q ? K2 : K1) - ab;

            unsigned int c = g_sub[p][q][t];
            ss[t] = c;
            __syncthreads();
            for (int off = 1; off < 1024; off <<= 1) {
                unsigned int v = (t + off < 1024) ? ss[t + off] : 0u;
                __syncthreads();
                ss[t] += v;
                __syncthreads();
            }
            unsigned int above = (t < 1023) ? ss[t + 1] : 0u;
            if (t == 0) g_key[p][q] = WLO + (bin << W1SHIFT);
            __syncthreads();
            if (above < r && r <= above + c)
                g_key[p][q] = WLO + (bin << W1SHIFT) + (unsigned)t;
            __syncthreads();
        }
    } else {
        // exact fallback: binary search on the key over the whole patch
        const float* base = g_blur + ((p >> 3) * 512) * HW + (p & 7) * 512;
        for (int q = 0; q < 2; q++) {
            const unsigned int K = q ? K2 : K1;
            unsigned int lo = 0u, hi = 0x40000000u;
            while (hi - lo > 1u) {
                unsigned int mid = lo + ((hi - lo) >> 1);
                unsigned int cnt = 0;
                for (int i = t; i < 512 * 512; i += 1024) {
                    unsigned int key = __float_as_uint(base[(i >> 9) * HW + (i & 511)]);
                    cnt += (key >= mid) ? 1u : 0u;
                }
                #pragma unroll
                for (int off = 16; off; off >>= 1)
                    cnt += __shfl_down_sync(0xffffffffu, cnt, off);
                if (lane == 0) ss[wid] = cnt;
                __syncthreads();
                if (t == 0) {
                    unsigned int s = 0;
                    for (int i = 0; i < 32; i++) s += ss[i];
                    scnt = s;
                }
                __syncthreads();
                if (scnt >= K) lo = mid; else hi = mid;
                __syncthreads();
            }
            if (t == 0) g_key[p][q] = lo;
            __syncthreads();
        }
    }
}

// ---------------- K4: sequential threshold walk (bit-faithful, unrolled chain) ----------------
__device__ __forceinline__ float walk_down(float th, float A) {
    for (int g = 0; g < 20000; g++) {
        if (!(A <= th)) return th;
        float t1  = th  - 0.0005f; if (A > t1)  return t1;
        float t2  = t1  - 0.0005f; if (A > t2)  return t2;
        float t3  = t2  - 0.0005f; if (A > t3)  return t3;
        float t4  = t3  - 0.0005f; if (A > t4)  return t4;
        float t5  = t4  - 0.0005f; if (A > t5)  return t5;
        float t6  = t5  - 0.0005f; if (A > t6)  return t6;
        float t7  = t6  - 0.0005f; if (A > t7)  return t7;
        float t8  = t7  - 0.0005f; if (A > t8)  return t8;
        float t9  = t8  - 0.0005f; if (A > t9)  return t9;
        float t10 = t9  - 0.0005f; if (A > t10) return t10;
        float t11 = t10 - 0.0005f; if (A > t11) return t11;
        float t12 = t11 - 0.0005f; if (A > t12) return t12;
        float t13 = t12 - 0.0005f; if (A > t13) return t13;
        float t14 = t13 - 0.0005f; if (A > t14) return t14;
        float t15 = t14 - 0.0005f; if (A > t15) return t15;
        th = t15 - 0.0005f;
    }
    return th;
}
__device__ __forceinline__ float walk_up(float th, float B) {
    for (int g = 0; g < 20000; g++) {
        if (!(B > th)) return th;
        float t1  = th  + 0.0005f; if (B <= t1)  return t1;
        float t2  = t1  + 0.0005f; if (B <= t2)  return t2;
        float t3  = t2  + 0.0005f; if (B <= t3)  return t3;
        float t4  = t3  + 0.0005f; if (B <= t4)  return t4;
        float t5  = t4  + 0.0005f; if (B <= t5)  return t5;
        float t6  = t5  + 0.0005f; if (B <= t6)  return t6;
        float t7  = t6  + 0.0005f; if (B <= t7)  return t7;
        float t8  = t7  + 0.0005f; if (B <= t8)  return t8;
        float t9  = t8  + 0.0005f; if (B <= t9)  return t9;
        float t10 = t9  + 0.0005f; if (B <= t10) return t10;
        float t11 = t10 + 0.0005f; if (B <= t11) return t11;
        float t12 = t11 + 0.0005f; if (B <= t12) return t12;
        float t13 = t12 + 0.0005f; if (B <= t13) return t13;
        float t14 = t13 + 0.0005f; if (B <= t14) return t14;
        float t15 = t14 + 0.0005f; if (B <= t15) return t15;
        th = t15 + 0.0005f;
    }
    return th;
}

__global__ void walk() {
    if (blockIdx.x == 0 && threadIdx.x == 0) {
        float th = 0.5f;
        for (int p = 0; p < NPATCH; p++) {
            float A = __uint_as_float(g_key[p][0]);
            float B = __uint_as_float(g_key[p][1]);
            th = walk_down(th, A);
            th = walk_up(th, B);
            g_th[p] = th;
        }
    }
}

// ---------------- K5: bit-packed binarize + close (dilate5, erode5) ----------------
#define CTW  256
#define CTH  128
#define WPR  10
#define TROWS 136
__global__ __launch_bounds__(256) void close_k(float* __restrict__ out) {
    __shared__ unsigned int A[TROWS][WPR];
    __shared__ unsigned int B[TROWS][WPR];
    __shared__ float sth[NPATCH];
    const int t = threadIdx.x;
    if (t < NPATCH) sth[t] = g_th[t];
    __syncthreads();

    const int gx0 = blockIdx.x * CTW;
    const int gy0 = blockIdx.y * CTH;
    const int lane = t & 31, wid = t >> 5;

    for (int idx = wid; idx < TROWS * WPR; idx += 8) {
        int r = idx / WPR, wc = idx % WPR;
        int gy = gy0 + r - 4;
        int gx = gx0 + (wc - 1) * 32 + lane;
        unsigned int bit = 0;
        if ((unsigned)gy < HW && (unsigned)gx < HW) {
            float bl = g_blur[gy * HW + gx];
            bit = (bl > sth[((gy >> 9) << 3) + (gx >> 9)]) ? 1u : 0u;
        }
        unsigned int word = __ballot_sync(0xffffffffu, bit);
        if (lane == 0) A[r][wc] = word;
    }
    __syncthreads();

    for (int i = t; i < TROWS * WPR; i += 256) {
        int r = i / WPR, wc = i % WPR;
        unsigned int wv = A[r][wc];
        unsigned int lw = wc > 0       ? A[r][wc - 1] : 0u;
        unsigned int rw = wc < WPR - 1 ? A[r][wc + 1] : 0u;
        B[r][wc] = wv | __funnelshift_r(wv, rw, 1) | __funnelshift_r(wv, rw, 2)
                      | __funnelshift_l(lw, wv, 1) | __funnelshift_l(lw, wv, 2);
    }
    __syncthreads();

    for (int i = t; i < TROWS * WPR; i += 256) {
        int r = i / WPR, wc = i % WPR;
        unsigned int d = 0u;
        if (r >= 2 && r < TROWS - 2)
            d = B[r-2][wc] | B[r-1][wc] | B[r][wc] | B[r+1][wc] | B[r+2][wc];
        int gy = gy0 + r - 4;
        bool xout = (wc == 0 && gx0 == 0) || (wc == WPR - 1 && gx0 + CTW == HW);
        if ((unsigned)gy >= HW || xout) d = 0xffffffffu;
        A[r][wc] = d;
    }
    __syncthreads();

    for (int i = t; i < TROWS * WPR; i += 256) {
        int r = i / WPR, wc = i % WPR;
        unsigned int wv = A[r][wc];
        unsigned int lw = wc > 0       ? A[r][wc - 1] : 0xffffffffu;
        unsigned int rw = wc < WPR - 1 ? A[r][wc + 1] : 0xffffffffu;
        B[r][wc] = wv & __funnelshift_r(wv, rw, 1) & __funnelshift_r(wv, rw, 2)
                      & __funnelshift_l(lw, wv, 1) & __funnelshift_l(lw, wv, 2);
    }
    __syncthreads();

    for (int i = t; i < CTH * 8; i += 256) {
        int r = (i >> 3) + 4, wc = (i & 7) + 1;
        unsigned int v = B[r-2][wc] & B[r-1][wc] & B[r][wc] & B[r+1][wc] & B[r+2][wc];
        int gy = gy0 + r - 4;
        int gx = gx0 + (wc - 1) * 32;
        float4* o = (float4*)&out[gy * HW + gx];
        #pragma unroll
        for (int q = 0; q < 8; q++) {
            float4 fv;
            fv.x = (v >> (q * 4 + 0)) & 1u ? 1.0f : 0.0f;
            fv.y = (v >> (q * 4 + 1)) & 1u ? 1.0f : 0.0f;
            fv.z = (v >> (q * 4 + 2)) & 1u ? 1.0f : 0.0f;
            fv.w = (v >> (q * 4 + 3)) & 1u ? 1.0f : 0.0f;
            o[q] = fv;
        }
    }
}

// ---------------- launch ----------------
extern "C" void kernel_launch(void* const* d_in, const int* in_sizes, int n_in,
                              void* d_out, int out_size) {
    const float* x  = (const float*)d_in[0];
    const float* bk = (const float*)d_in[1];
    float* out = (float*)d_out;
    (void)in_sizes; (void)n_in; (void)out_size;

    blur_hist<<<dim3(HW / 512, HW / RPB), 128>>>(x, bk);
    coarse_select_win<<<NPATCH, 1024>>>();
    refine_pass<<<2048, 256>>>();
    refine_select_fb<<<NPATCH, 1024>>>();
    walk<<<1, 32>>>();
    close_k<<<dim3(HW / CTW, HW / CTH), 256>>>(out);
}

// round 12
// speedup vs baseline: 1.4497x; 1.1659x over previous
#include <cuda_runtime.h>

// ---------------- problem constants ----------------
#define HW      4096
#define NPIX    (HW*HW)
#define NPATCH  64
#define K1      31458u   // loop1 continues iff count(v>th) <= 31457  <=>  v_(31458) <= th
#define K2      20972u   // loop2 continues iff count(v>th) >= 20972  <=>  v_(20972) >  th

// value window (verified per-patch; exact fallback if violated)
#define WLO     0x3F0E0000u   // ~0.5547
#define WHI     0x3F1A0000u   // ~0.6016
#define WSPAN   0xC0000u
#define NW1     768           // level-1 bins of 1024 keys each
#define W1SHIFT 10

#define RPB     16            // rows per blur block
#define BPPY    (512 / RPB)   // blur blocks per patch, vertically (32)
#define NBLK    (8 * (HW / RPB))   // total blur blocks (2048)

// ---------------- device scratch ----------------
__device__ float        g_blur[NPIX];
__device__ unsigned int g_bhist[NBLK][NW1];      // per-block hist (plain stores, no zeroing)
__device__ unsigned int g_babove[NBLK];
__device__ int          g_need [NPATCH];         // exact-fallback flag (plain store)
__device__ unsigned int g_sub  [NPATCH][2][1024];
__device__ unsigned int g_sel  [NPATCH][4];      // bin1, above1, bin2, above2
__device__ unsigned int g_key  [NPATCH][2];
__device__ float        g_th   [NPATCH];

// ---------------- K1: blur (circular register window, fully unrolled) + per-block hist ----
// 128 threads x 4 cols = 512 cols (one patch width), RPB rows per block.
// Per-pixel 25-tap fmaf chain IDENTICAL to the passing version (kw outer, kh inner).
__device__ __forceinline__ void load_row(float* dst, const float* __restrict__ x,
                                         int yy, int c0, bool safe) {
    if (yy < 0 || yy >= HW) {
        #pragma unroll
        for (int j = 0; j < 12; j++) dst[j] = 0.0f;
    } else if (safe) {
        const float4* p = (const float4*)&x[yy * HW + c0 - 4];
        float4 a = __ldg(p), b = __ldg(p + 1), c = __ldg(p + 2);
        dst[0]=a.x; dst[1]=a.y; dst[2]=a.z;  dst[3]=a.w;
        dst[4]=b.x; dst[5]=b.y; dst[6]=b.z;  dst[7]=b.w;
        dst[8]=c.x; dst[9]=c.y; dst[10]=c.z; dst[11]=c.w;
    } else {
        #pragma unroll
        for (int j = 0; j < 12; j++) {
            int cc = c0 - 4 + j;
            dst[j] = (cc >= 0 && cc < HW) ? __ldg(&x[yy * HW + cc]) : 0.0f;
        }
    }
}

__global__ __launch_bounds__(128) void blur_hist(const float* __restrict__ x,
                                                 const float* __restrict__ bk) {
    __shared__ unsigned int wh[NW1];
    __shared__ unsigned int sred[4];
    for (int i = threadIdx.x; i < NW1; i += 128) wh[i] = 0u;
    __syncthreads();

    const float w  = bk[0];
    const int   c0 = blockIdx.x * 512 + threadIdx.x * 4;
    const int   y0 = blockIdx.y * RPB;
    const int   blk = blockIdx.y * 8 + blockIdx.x;
    const bool  safe = (c0 >= 4) && (c0 <= HW - 9);
    const int   lane = threadIdx.x & 31;
    unsigned int cntAbove = 0;

    float f[5][12];
    #pragma unroll
    for (int i = 0; i < 4; i++) load_row(f[i], x, y0 - 2 + i, c0, safe);

    #pragma unroll
    for (int k = 0; k < RPB; k++) {
        const int y = y0 + k;
        load_row(f[(k + 4) % 5], x, y + 2, c0, safe);

        float4 o;
        float* op = (float*)&o;
        #pragma unroll
        for (int u = 0; u < 4; u++) {
            float acc = 0.0f;
            #pragma unroll
            for (int j = 0; j < 5; j++)        // kw outer
                #pragma unroll
                for (int i = 0; i < 5; i++)    // kh inner (fastest) — Eigen order
                    acc = fmaf(f[(k + i) % 5][u + j + 2], w, acc);
            op[u] = acc;
            unsigned int key = __float_as_uint(acc);
            cntAbove += (key >= WHI) ? 1u : 0u;
            if (key - WLO < WSPAN)
                atomicAdd(&wh[(key - WLO) >> W1SHIFT], 1u);
        }
        *(float4*)&g_blur[y * HW + c0] = o;
    }

    #pragma unroll
    for (int off = 16; off; off >>= 1)
        cntAbove += __shfl_down_sync(0xffffffffu, cntAbove, off);
    if (lane == 0) sred[threadIdx.x >> 5] = cntAbove;
    __syncthreads();
    if (threadIdx.x == 0)
        g_babove[blk] = sred[0] + sred[1] + sred[2] + sred[3];
    for (int i = threadIdx.x; i < NW1; i += 128)
        g_bhist[blk][i] = wh[i];
}

// ---------------- K2: sum block hists, locate level-1 bins, zero g_sub ----------------
__global__ __launch_bounds__(1024) void coarse_select_win() {
    __shared__ unsigned int ss[1024];
    __shared__ unsigned int sga;
    const int p = blockIdx.x, t = threadIdx.x;
    const int pr = p >> 3, pc = p & 7;

    // zero the sub-hist for this patch (runs before refine_pass)
    g_sub[p][0][t] = 0u;
    g_sub[p][1][t] = 0u;

    // sum the per-block above-counts (BPPY = 32 -> one warp)
    if (t < BPPY) {
        unsigned int a = g_babove[(pr * BPPY + t) * 8 + pc];
        #pragma unroll
        for (int off = 16; off; off >>= 1)
            a += __shfl_down_sync(0xffffffffu, a, off);
        if (t == 0) sga = a;
    }

    // sum the per-block hists
    unsigned int c = 0;
    if (t < NW1) {
        #pragma unroll 4
        for (int s = 0; s < BPPY; s++)
            c += g_bhist[(pr * BPPY + s) * 8 + pc][t];
    }
    ss[t] = c;
    __syncthreads();
    for (int off = 1; off < 1024; off <<= 1) {   // inclusive suffix scan
        unsigned int v = (t + off < 1024) ? ss[t + off] : 0u;
        __syncthreads();
        ss[t] += v;
        __syncthreads();
    }
    const unsigned int ga = sga;
    const unsigned int total_in = ss[0];
    unsigned int above = ((t < 1023) ? ss[t + 1] : 0u) + ga;

    if (t == 0)
        g_need[p] = (ga >= K2) || (ga + total_in < K1) ? 1 : 0;

    if (above < K1 && K1 <= above + c) { g_sel[p][0] = (unsigned)t; g_sel[p][1] = above; }
    if (above < K2 && K2 <= above + c) { g_sel[p][2] = (unsigned)t; g_sel[p][3] = above; }
}

// ---------------- K3a: sub-histogram, full re-read of g_blur (2x float4/iter) --------------
__global__ __launch_bounds__(256) void refine_pass() {
    __shared__ unsigned int sbin[NPATCH][2];
    if (threadIdx.x < NPATCH) {
        sbin[threadIdx.x][0] = g_sel[threadIdx.x][0];
        sbin[threadIdx.x][1] = g_sel[threadIdx.x][2];
    }
    __syncthreads();
    const float4* b4 = (const float4*)g_blur;
    const unsigned int n4 = NPIX / 4;              // 4M
    const unsigned int stride = gridDim.x * 256;   // 524288; n4/stride = 8 exactly
    for (unsigned int i = blockIdx.x * 256 + threadIdx.x; i < n4; i += 2 * stride) {
        float4 va = __ldg(&b4[i]);
        float4 vb = __ldg(&b4[i + stride]);
        #pragma unroll
        for (int h = 0; h < 2; h++) {
            unsigned int ii = h ? (i + stride) : i;
            const float* vp = h ? (const float*)&vb : (const float*)&va;
            int y = ii >> 10;
            int p = ((y >> 9) << 3) + ((ii & 1023u) >> 7);
            #pragma unroll
            for (int u = 0; u < 4; u++) {
                unsigned int wk = __float_as_uint(vp[u]) - WLO;
                if (wk < WSPAN) {
                    unsigned int bin = wk >> W1SHIFT;
                    if (bin == sbin[p][0]) atomicAdd(&g_sub[p][0][wk & 1023u], 1u);
                    if (bin == sbin[p][1]) atomicAdd(&g_sub[p][1][wk & 1023u], 1u);
                }
            }
        }
    }
}

// ---------------- K3b: exact key within level-1 bin, with merged exact fallback ---------------
__global__ __launch_bounds__(1024) void refine_select_fb() {
    __shared__ unsigned int ss[1024];
    __shared__ unsigned int scnt;
    const int p = blockIdx.x, t = threadIdx.x;
    const int lane = t & 31, wid = t >> 5;

    if (!g_need[p]) {
        for (int q = 0; q < 2; q++) {
            const unsigned int bin = g_sel[p][q * 2];
            const unsigned int ab  = g_sel[p][q * 2 + 1];
            const unsigned int r   = (q ? K2 : K1) - ab;

            unsigned int c = g_sub[p][q][t];
            ss[t] = c;
            __syncthreads();
            for (int off = 1; off < 1024; off <<= 1) {
                unsigned int v = (t + off < 1024) ? ss[t + off] : 0u;
                __syncthreads();
                ss[t] += v;
                __syncthreads();
            }
            unsigned int above = (t < 1023) ? ss[t + 1] : 0u;
            if (t == 0) g_key[p][q] = WLO + (bin << W1SHIFT);
            __syncthreads();
            if (above < r && r <= above + c)
                g_key[p][q] = WLO + (bin << W1SHIFT) + (unsigned)t;
            __syncthreads();
        }
    } else {
        // exact fallback: binary search on the key over the whole patch
        const float* base = g_blur + ((p >> 3) * 512) * HW + (p & 7) * 512;
        for (int q = 0; q < 2; q++) {
            const unsigned int K = q ? K2 : K1;
            unsigned int lo = 0u, hi = 0x40000000u;
            while (hi - lo > 1u) {
                unsigned int mid = lo + ((hi - lo) >> 1);
                unsigned int cnt = 0;
                for (int i = t; i < 512 * 512; i += 1024) {
                    unsigned int key = __float_as_uint(base[(i >> 9) * HW + (i & 511)]);
                    cnt += (key >= mid) ? 1u : 0u;
                }
                #pragma unroll
                for (int off = 16; off; off >>= 1)
                    cnt += __shfl_down_sync(0xffffffffu, cnt, off);
                if (lane == 0) ss[wid] = cnt;
                __syncthreads();
                if (t == 0) {
                    unsigned int s = 0;
                    for (int i = 0; i < 32; i++) s += ss[i];
                    scnt = s;
                }
                __syncthreads();
                if (scnt >= K) lo = mid; else hi = mid;
                __syncthreads();
            }
            if (t == 0) g_key[p][q] = lo;
            __syncthreads();
        }
    }
}

// ---------------- K4: sequential threshold walk (bit-faithful, unrolled chain) ----------------
__device__ __forceinline__ float walk_down(float th, float A) {
    for (int g = 0; g < 20000; g++) {
        if (!(A <= th)) return th;
        float t1  = th  - 0.0005f; if (A > t1)  return t1;
        float t2  = t1  - 0.0005f; if (A > t2)  return t2;
        float t3  = t2  - 0.0005f; if (A > t3)  return t3;
        float t4  = t3  - 0.0005f; if (A > t4)  return t4;
        float t5  = t4  - 0.0005f; if (A > t5)  return t5;
        float t6  = t5  - 0.0005f; if (A > t6)  return t6;
        float t7  = t6  - 0.0005f; if (A > t7)  return t7;
        float t8  = t7  - 0.0005f; if (A > t8)  return t8;
        float t9  = t8  - 0.0005f; if (A > t9)  return t9;
        float t10 = t9  - 0.0005f; if (A > t10) return t10;
        float t11 = t10 - 0.0005f; if (A > t11) return t11;
        float t12 = t11 - 0.0005f; if (A > t12) return t12;
        float t13 = t12 - 0.0005f; if (A > t13) return t13;
        float t14 = t13 - 0.0005f; if (A > t14) return t14;
        float t15 = t14 - 0.0005f; if (A > t15) return t15;
        th = t15 - 0.0005f;
    }
    return th;
}
__device__ __forceinline__ float walk_up(float th, float B) {
    for (int g = 0; g < 20000; g++) {
        if (!(B > th)) return th;
        float t1  = th  + 0.0005f; if (B <= t1)  return t1;
        float t2  = t1  + 0.0005f; if (B <= t2)  return t2;
        float t3  = t2  + 0.0005f; if (B <= t3)  return t3;
        float t4  = t3  + 0.0005f; if (B <= t4)  return t4;
        float t5  = t4  + 0.0005f; if (B <= t5)  return t5;
        float t6  = t5  + 0.0005f; if (B <= t6)  return t6;
        float t7  = t6  + 0.0005f; if (B <= t7)  return t7;
        float t8  = t7  + 0.0005f; if (B <= t8)  return t8;
        float t9  = t8  + 0.0005f; if (B <= t9)  return t9;
        float t10 = t9  + 0.0005f; if (B <= t10) return t10;
        float t11 = t10 + 0.0005f; if (B <= t11) return t11;
        float t12 = t11 + 0.0005f; if (B <= t12) return t12;
        float t13 = t12 + 0.0005f; if (B <= t13) return t13;
        float t14 = t13 + 0.0005f; if (B <= t14) return t14;
        float t15 = t14 + 0.0005f; if (B <= t15) return t15;
        th = t15 + 0.0005f;
    }
    return th;
}

__global__ void walk() {
    if (blockIdx.x == 0 && threadIdx.x == 0) {
        float th = 0.5f;
        for (int p = 0; p < NPATCH; p++) {
            float A = __uint_as_float(g_key[p][0]);
            float B = __uint_as_float(g_key[p][1]);
            th = walk_down(th, A);
            th = walk_up(th, B);
            g_th[p] = th;
        }
    }
}

// ---------------- K5: bit-packed binarize + close (dilate5, erode5) ----------------
#define CTW  256
#define CTH  128
#define WPR  10
#define TROWS 136
__global__ __launch_bounds__(256) void close_k(float* __restrict__ out) {
    __shared__ unsigned int A[TROWS][WPR];
    __shared__ unsigned int B[TROWS][WPR];
    __shared__ float sth[NPATCH];
    const int t = threadIdx.x;
    if (t < NPATCH) sth[t] = g_th[t];
    __syncthreads();

    const int gx0 = blockIdx.x * CTW;
    const int gy0 = blockIdx.y * CTH;
    const int lane = t & 31, wid = t >> 5;

    // binarize: per warp-row, issue all 10 guarded loads first (MLP=10), then ballots
    for (int rr = 0; rr < TROWS / 8; rr++) {       // 17 rows per warp
        const int r  = wid + rr * 8;
        const int gy = gy0 + r - 4;
        const bool gyok = (unsigned)gy < HW;
        float v[WPR];
        #pragma unroll
        for (int wc = 0; wc < WPR; wc++) {
            int gx = gx0 + (wc - 1) * 32 + lane;
            v[wc] = (gyok && (unsigned)gx < HW) ? g_blur[gy * HW + gx] : 0.0f;
        }
        #pragma unroll
        for (int wc = 0; wc < WPR; wc++) {
            int gx = gx0 + (wc - 1) * 32 + lane;
            unsigned int bit = 0;
            if (gyok && (unsigned)gx < HW)
                bit = (v[wc] > sth[((gy >> 9) << 3) + (gx >> 9)]) ? 1u : 0u;
            unsigned int word = __ballot_sync(0xffffffffu, bit);
            if (lane == 0) A[r][wc] = word;
        }
    }
    __syncthreads();

    for (int i = t; i < TROWS * WPR; i += 256) {
        int r = i / WPR, wc = i % WPR;
        unsigned int wv = A[r][wc];
        unsigned int lw = wc > 0       ? A[r][wc - 1] : 0u;
        unsigned int rw = wc < WPR - 1 ? A[r][wc + 1] : 0u;
        B[r][wc] = wv | __funnelshift_r(wv, rw, 1) | __funnelshift_r(wv, rw, 2)
                      | __funnelshift_l(lw, wv, 1) | __funnelshift_l(lw, wv, 2);
    }
    __syncthreads();

    for (int i = t; i < TROWS * WPR; i += 256) {
        int r = i / WPR, wc = i % WPR;
        unsigned int d = 0u;
        if (r >= 2 && r < TROWS - 2)
            d = B[r-2][wc] | B[r-1][wc] | B[r][wc] | B[r+1][wc] | B[r+2][wc];
        int gy = gy0 + r - 4;
        bool xout = (wc == 0 && gx0 == 0) || (wc == WPR - 1 && gx0 + CTW == HW);
        if ((unsigned)gy >= HW || xout) d = 0xffffffffu;
        A[r][wc] = d;
    }
    __syncthreads();

    for (int i = t; i < TROWS * WPR; i += 256) {
        int r = i / WPR, wc = i % WPR;
        unsigned int wv = A[r][wc];
        unsigned int lw = wc > 0       ? A[r][wc - 1] : 0xffffffffu;
        unsigned int rw = wc < WPR - 1 ? A[r][wc + 1] : 0xffffffffu;
        B[r][wc] = wv & __funnelshift_r(wv, rw, 1) & __funnelshift_r(wv, rw, 2)
                      & __funnelshift_l(lw, wv, 1) & __funnelshift_l(lw, wv, 2);
    }
    __syncthreads();

    for (int i = t; i < CTH * 8; i += 256) {
        int r = (i >> 3) + 4, wc = (i & 7) + 1;
        unsigned int v = B[r-2][wc] & B[r-1][wc] & B[r][wc] & B[r+1][wc] & B[r+2][wc];
        int gy = gy0 + r - 4;
        int gx = gx0 + (wc - 1) * 32;
        float4* o = (float4*)&out[gy * HW + gx];
        #pragma unroll
        for (int q = 0; q < 8; q++) {
            float4 fv;
            fv.x = (v >> (q * 4 + 0)) & 1u ? 1.0f : 0.0f;
            fv.y = (v >> (q * 4 + 1)) & 1u ? 1.0f : 0.0f;
            fv.z = (v >> (q * 4 + 2)) & 1u ? 1.0f : 0.0f;
            fv.w = (v >> (q * 4 + 3)) & 1u ? 1.0f : 0.0f;
            o[q] = fv;
        }
    }
}

// ---------------- launch ----------------
extern "C" void kernel_launch(void* const* d_in, const int* in_sizes, int n_in,
                              void* d_out, int out_size) {
    const float* x  = (const float*)d_in[0];
    const float* bk = (const float*)d_in[1];
    float* out = (float*)d_out;
    (void)in_sizes; (void)n_in; (void)out_size;

    blur_hist<<<dim3(HW / 512, HW / RPB), 128>>>(x, bk);
    coarse_select_win<<<NPATCH, 1024>>>();
    refine_pass<<<2048, 256>>>();
    refine_select_fb<<<NPATCH, 1024>>>();
    walk<<<1, 32>>>();
    close_k<<<dim3(HW / CTW, HW / CTH), 256>>>(out);
}